// round 13
// baseline (speedup 1.0000x reference)
#include <cuda_runtime.h>
#include <math.h>
#include <stdint.h>

// Problem constants
#define NU      50000
#define NI      50000
#define M_TOT   100000
#define IN_DIM  256
#define HID     128
#define OUT_DIM 64
#define NBIN    (NU + NI)
#define BCAP    32
#define OVF_CAP 8192
#define UGRP    5              // bin-groups per block in bin_acc_user

// ---------------------------------------------------------------------------
// Device scratch
// ---------------------------------------------------------------------------
__device__ float    g_h[(size_t)M_TOT * HID];
__device__ float    g_acc[(size_t)NU * HID];       // only written on overflow
__device__ uint32_t g_Wt[IN_DIM * HID];            // W in tf32 bits, B-FRAGMENT layout
__device__ int      g_cnt[NBIN];                   // zero-init; re-zeroed by bin_acc
__device__ uint32_t g_bucket[(size_t)NBIN * BCAP];
__device__ int      g_ovfn;                        // reset by ovf_repair
__device__ uint2    g_ovf[OVF_CAP];

__device__ __forceinline__ float elu1(float x) { return x > 0.f ? x : expm1f(x); }

__device__ __forceinline__ uint32_t smem_u32(const void* p) {
    uint32_t a;
    asm("{ .reg .u64 t; cvta.to.shared.u64 t, %1; cvt.u32.u64 %0, t; }" : "=r"(a) : "l"(p));
    return a;
}

__device__ __forceinline__ void cp_async16(uint32_t dst_smem, const void* src) {
    asm volatile("cp.async.cg.shared.global [%0], [%1], 16;"
                 :: "r"(dst_smem), "l"(src) : "memory");
}
#define CP_COMMIT() asm volatile("cp.async.commit_group;" ::: "memory")

__device__ __forceinline__ uint32_t f2tf32(float v) {
    uint32_t t;
    asm("cvt.rna.tf32.f32 %0, %1;" : "=r"(t) : "f"(v));
    return t;
}

__device__ __forceinline__ float ldcg(const float* p) {
    float v;
    asm volatile("ld.global.cg.f32 %0, [%1];" : "=f"(v) : "l"(p));
    return v;
}

__device__ __forceinline__ void mma_tf32(float& d0, float& d1, float& d2, float& d3,
                                         uint32_t a0, uint32_t a1, uint32_t a2, uint32_t a3,
                                         uint32_t b0, uint32_t b1) {
    asm volatile(
        "mma.sync.aligned.m16n8k8.row.col.f32.tf32.tf32.f32 "
        "{%0,%1,%2,%3}, {%4,%5,%6,%7}, {%8,%9}, {%0,%1,%2,%3};"
        : "+f"(d0), "+f"(d1), "+f"(d2), "+f"(d3)
        : "r"(a0), "r"(a1), "r"(a2), "r"(a3), "r"(b0), "r"(b1));
}

// ---------------------------------------------------------------------------
// prep: convert W[k][n] -> tf32 bits in B-FRAGMENT layout (as R9).
// ---------------------------------------------------------------------------
__global__ void prep_kernel(const float* __restrict__ W, uint32_t* __restrict__ Wt) {
    int i = blockIdx.x * 256 + threadIdx.x;
    if (i >= IN_DIM * HID) return;
    int k = i >> 7;
    int n = i & 127;
    int c    = k >> 5;
    int ks   = (k >> 3) & 3;
    int slot = (k >> 2) & 1;
    int tig  = k & 3;
    int wn   = n >> 5;
    int nt   = (n >> 3) & 3;
    int gid  = n & 7;
    int lane = gid * 4 + tig;
    int idx  = c * 4096 + (((ks * 4 + wn) * 4 + nt) * 32 + lane) * 2 + slot;
    Wt[idx] = f2tf32(W[i]);
}

// ---------------------------------------------------------------------------
// Projection via mma.sync tf32, fragment-major smem (unchanged from R9).
// ---------------------------------------------------------------------------
#define KC       32
#define NCHUNK   (IN_DIM / KC)
#define BM       64
#define ASF_W    2112
#define BSF_W    4096
#define PROJ_SMEM ((2 * ASF_W + 2 * BSF_W) * 4)   // 49664 bytes

__device__ __forceinline__ void ldA_regs(const float* __restrict__ xu,
                                         const float* __restrict__ xi,
                                         int m0, int c, int tid, float4* r) {
#pragma unroll
    for (int L = 0; L < 2; L++) {
        int i = tid + L * 256;
        int row = i >> 3;
        int seg = i & 7;
        int gr = m0 + row;
        if (gr >= M_TOT) gr = M_TOT - 1;
        const float* src = (gr < NU) ? (xu + (size_t)gr * IN_DIM)
                                     : (xi + (size_t)(gr - NU) * IN_DIM);
        r[L] = *reinterpret_cast<const float4*>(src + c * KC + seg * 4);
    }
}

__device__ __forceinline__ void stA_smem(uint32_t* __restrict__ As, int tid,
                                         const float4* r) {
#pragma unroll
    for (int L = 0; L < 2; L++) {
        int i = tid + L * 256;
        int row = i >> 3;
        int seg = i & 7;
        int rg    = row >> 4;
        int gid   = row & 7;
        int slotb = (row >> 3) & 1;
        int ks    = seg >> 1;
        int slot  = slotb + 2 * (seg & 1);
        uint32_t* base = As + (rg * 4 + ks) * 132 + gid * 16 + slot;
        base[0]  = f2tf32(r[L].x);
        base[4]  = f2tf32(r[L].y);
        base[8]  = f2tf32(r[L].z);
        base[12] = f2tf32(r[L].w);
    }
}

__device__ __forceinline__ void ldB_cpasync(uint32_t sB, const uint32_t* __restrict__ Wt,
                                            int c, int tid) {
#pragma unroll
    for (int L = 0; L < 4; L++) {
        int i = tid + L * 256;
        cp_async16(sB + i * 16, Wt + (size_t)c * 4096 + i * 4);
    }
    CP_COMMIT();
}

__global__ __launch_bounds__(256, 3) void proj_mma_kernel(
    const float* __restrict__ xu, const float* __restrict__ xi,
    const uint32_t* __restrict__ Wt, const float* __restrict__ bias,
    float* __restrict__ h)
{
    extern __shared__ uint32_t smw[];
    uint32_t sb = smem_u32(smw);
    const int tid  = threadIdx.x;
    const int wid  = tid >> 5;
    const int lane = tid & 31;
    const int gid  = lane >> 2;
    const int tig  = lane & 3;
    const int wm   = wid >> 2;
    const int wn   = wid & 3;
    const int m0   = blockIdx.x * BM;

    float d[2][4][4];
#pragma unroll
    for (int i = 0; i < 2; i++)
#pragma unroll
        for (int j = 0; j < 4; j++)
#pragma unroll
            for (int q = 0; q < 4; q++) d[i][j][q] = 0.f;

    float4 rA[2];
    ldA_regs(xu, xi, m0, 0, tid, rA);
    ldB_cpasync(sb + (2 * ASF_W + 0 * BSF_W) * 4, Wt, 0, tid);
    ldB_cpasync(sb + (2 * ASF_W + 1 * BSF_W) * 4, Wt, 1, tid);

    for (int c = 0; c < NCHUNK; c++) {
        int s = c & 1;
        uint32_t* As = smw + s * ASF_W;
        const uint32_t* Bs = smw + 2 * ASF_W + s * BSF_W;

        stA_smem(As, tid, rA);
        if (c + 1 < NCHUNK) ldA_regs(xu, xi, m0, c + 1, tid, rA);

        if (c < NCHUNK - 1) asm volatile("cp.async.wait_group 1;" ::: "memory");
        else                asm volatile("cp.async.wait_group 0;" ::: "memory");
        __syncthreads();

#pragma unroll
        for (int ks = 0; ks < KC / 8; ks++) {
            uint32_t a[2][4];
#pragma unroll
            for (int mt = 0; mt < 2; mt++) {
                int rg = wm * 2 + mt;
                uint4 av = *reinterpret_cast<const uint4*>(
                    As + (rg * 4 + ks) * 132 + lane * 4);
                a[mt][0] = av.x; a[mt][1] = av.y; a[mt][2] = av.z; a[mt][3] = av.w;
            }
            uint32_t b[4][2];
#pragma unroll
            for (int nt = 0; nt < 4; nt++) {
                uint2 bv = *reinterpret_cast<const uint2*>(
                    Bs + (((ks * 4 + wn) * 4 + nt) * 32 + lane) * 2);
                b[nt][0] = bv.x; b[nt][1] = bv.y;
            }
#pragma unroll
            for (int mt = 0; mt < 2; mt++)
#pragma unroll
                for (int nt = 0; nt < 4; nt++)
                    mma_tf32(d[mt][nt][0], d[mt][nt][1], d[mt][nt][2], d[mt][nt][3],
                             a[mt][0], a[mt][1], a[mt][2], a[mt][3],
                             b[nt][0], b[nt][1]);
        }
        __syncthreads();
        if (c + 2 < NCHUNK)
            ldB_cpasync(sb + (2 * ASF_W + s * BSF_W) * 4, Wt, c + 2, tid);
    }

#pragma unroll
    for (int mt = 0; mt < 2; mt++) {
        int row0 = m0 + wm * 32 + mt * 16 + gid;
        int row1 = row0 + 8;
#pragma unroll
        for (int nt = 0; nt < 4; nt++) {
            int col = wn * 32 + nt * 8 + tig * 2;
            float2 bv = *reinterpret_cast<const float2*>(bias + col);
            if (row0 < M_TOT) {
                float2 v = make_float2(d[mt][nt][0] + bv.x, d[mt][nt][1] + bv.y);
                *reinterpret_cast<float2*>(h + (size_t)row0 * HID + col) = v;
            }
            if (row1 < M_TOT) {
                float2 v = make_float2(d[mt][nt][2] + bv.x, d[mt][nt][3] + bv.y);
                *reinterpret_cast<float2*>(h + (size_t)row1 * HID + col) = v;
            }
        }
    }
}

// ---------------------------------------------------------------------------
// Fill destination buckets from the three edge lists.
// ---------------------------------------------------------------------------
__global__ void fill_bucket_kernel(const int2* __restrict__ e_uu, int Euu,
                                   const int2* __restrict__ e_iu, int Eiu,
                                   const int2* __restrict__ e_ui, int Eui) {
    int e = blockIdx.x * 256 + threadIdx.x;
    int tot = Euu + Eiu + Eui;
    if (e >= tot) return;
    int2 ed;
    int bin;
    uint32_t val;
    if (e < Euu) {
        ed = __ldg(&e_uu[e]);             bin = ed.y;      val = (uint32_t)ed.x;
    } else if (e < Euu + Eiu) {
        ed = __ldg(&e_iu[e - Euu]);       bin = ed.y;      val = (uint32_t)ed.x | 0x80000000u;
    } else {
        ed = __ldg(&e_ui[e - Euu - Eiu]); bin = NU + ed.y; val = (uint32_t)ed.x;
    }
    int pos = atomicAdd(&g_cnt[bin], 1);
    if (pos < BCAP) {
        g_bucket[(size_t)bin * BCAP + pos] = val;
    } else {
        int o = atomicAdd(&g_ovfn, 1);
        if (o < OVF_CAP) g_ovf[o] = make_uint2((uint32_t)bin, val);
    }
}

// ---------------------------------------------------------------------------
// USER bins, FUSED with output GEMM, grid-strided (UGRP groups of 16 bins per
// block). W_out staged once per block. 2 bins/warp per group.
// ---------------------------------------------------------------------------
__global__ __launch_bounds__(256) void bin_acc_user_kernel(
    const float* __restrict__ h,
    const float* __restrict__ al_uu, const float* __restrict__ ar_uu,
    const float* __restrict__ al_iu, const float* __restrict__ ar_iu,
    const float* __restrict__ Wout, const float* __restrict__ bout,
    float* __restrict__ acc_u, float* __restrict__ out)
{
    __shared__ float Ws[HID][OUT_DIM];      // 32 KB
    __shared__ float sRow[8][2][HID];       // 8 KB

    const int tid  = threadIdx.x;
    const int wid  = tid >> 5;
    const int lane = tid & 31;
    const int have_ovf = g_ovfn;

#pragma unroll
    for (int L = 0; L < 8; L++) {
        int idx = tid + L * 256;
        reinterpret_cast<float4*>(&Ws[0][0])[idx] =
            reinterpret_cast<const float4*>(Wout)[idx];
    }
    __syncthreads();

    const float4* h4 = reinterpret_cast<const float4*>(h);
    const int b  = lane >> 4;
    const int j0 = (lane & 15) * 4;
    const float4 bv = *reinterpret_cast<const float4*>(bout + j0);

    for (int g = 0; g < UGRP; g++) {
        int bin0 = (blockIdx.x * UGRP + g) * 16 + 2 * wid;   // NU = 625*UGRP*16
        int bin1 = bin0 + 1;

        int n0 = __ldg(&g_cnt[bin0]); if (n0 > BCAP) n0 = BCAP;
        int n1 = __ldg(&g_cnt[bin1]); if (n1 > BCAP) n1 = BCAP;
        if (lane < 2) g_cnt[bin0 + lane] = 0;

        float al0 = 0.f, ar0 = 0.f, al1 = 0.f, ar1 = 0.f;
        uint32_t ro0 = 0, ro1 = 0;
        if (lane < n0) {
            uint32_t v = __ldg(&g_bucket[(size_t)bin0 * BCAP + lane]);
            uint32_t src = v & 0x7FFFFFFFu;
            if (v & 0x80000000u) { al0 = __ldg(al_iu); ar0 = __ldg(ar_iu); ro0 = NU + src; }
            else                 { al0 = __ldg(al_uu); ar0 = __ldg(ar_uu); ro0 = src; }
        }
        if (lane < n1) {
            uint32_t v = __ldg(&g_bucket[(size_t)bin1 * BCAP + lane]);
            uint32_t src = v & 0x7FFFFFFFu;
            if (v & 0x80000000u) { al1 = __ldg(al_iu); ar1 = __ldg(ar_iu); ro1 = NU + src; }
            else                 { al1 = __ldg(al_uu); ar1 = __ldg(ar_uu); ro1 = src; }
        }

        float coef0 = ar0, coef1 = ar1;
#pragma unroll
        for (int o = 16; o; o >>= 1) {
            coef0 += __shfl_xor_sync(0xFFFFFFFFu, coef0, o);
            coef1 += __shfl_xor_sync(0xFFFFFFFFu, coef1, o);
        }

        float4 p0 = make_float4(0.f, 0.f, 0.f, 0.f);
        float4 q0 = make_float4(0.f, 0.f, 0.f, 0.f);
        float4 p1 = make_float4(0.f, 0.f, 0.f, 0.f);
        float4 q1 = make_float4(0.f, 0.f, 0.f, 0.f);

        int nmax = n0 > n1 ? n0 : n1;
        for (int j = 0; j < nmax; j += 2) {
            uint32_t rA0 = __shfl_sync(0xFFFFFFFFu, ro0, j);
            float    aA0 = __shfl_sync(0xFFFFFFFFu, al0, j);
            uint32_t rB0 = __shfl_sync(0xFFFFFFFFu, ro0, (j + 1) & 31);
            float    aB0 = __shfl_sync(0xFFFFFFFFu, al0, (j + 1) & 31);
            uint32_t rA1 = __shfl_sync(0xFFFFFFFFu, ro1, j);
            float    aA1 = __shfl_sync(0xFFFFFFFFu, al1, j);
            uint32_t rB1 = __shfl_sync(0xFFFFFFFFu, ro1, (j + 1) & 31);
            float    aB1 = __shfl_sync(0xFFFFFFFFu, al1, (j + 1) & 31);
            if (j     >= n0) { aA0 = 0.f; rA0 = 0; }
            if (j + 1 >= n0) { aB0 = 0.f; rB0 = 0; }
            if (j     >= n1) { aA1 = 0.f; rA1 = 0; }
            if (j + 1 >= n1) { aB1 = 0.f; rB1 = 0; }
            float4 vA0 = __ldg(h4 + (size_t)rA0 * 32 + lane);
            float4 vB0 = __ldg(h4 + (size_t)rB0 * 32 + lane);
            float4 vA1 = __ldg(h4 + (size_t)rA1 * 32 + lane);
            float4 vB1 = __ldg(h4 + (size_t)rB1 * 32 + lane);
            p0.x += aA0 * vA0.x; p0.y += aA0 * vA0.y; p0.z += aA0 * vA0.z; p0.w += aA0 * vA0.w;
            q0.x += aB0 * vB0.x; q0.y += aB0 * vB0.y; q0.z += aB0 * vB0.z; q0.w += aB0 * vB0.w;
            p1.x += aA1 * vA1.x; p1.y += aA1 * vA1.y; p1.z += aA1 * vA1.z; p1.w += aA1 * vA1.w;
            q1.x += aB1 * vB1.x; q1.y += aB1 * vB1.y; q1.z += aB1 * vB1.z; q1.w += aB1 * vB1.w;
        }

        float4 hd0 = __ldg(h4 + (size_t)bin0 * 32 + lane);
        float4 hd1 = __ldg(h4 + (size_t)bin1 * 32 + lane);
        float4 s0, s1;
        s0.x = p0.x + q0.x + coef0 * hd0.x;
        s0.y = p0.y + q0.y + coef0 * hd0.y;
        s0.z = p0.z + q0.z + coef0 * hd0.z;
        s0.w = p0.w + q0.w + coef0 * hd0.w;
        s1.x = p1.x + q1.x + coef1 * hd1.x;
        s1.y = p1.y + q1.y + coef1 * hd1.y;
        s1.z = p1.z + q1.z + coef1 * hd1.z;
        s1.w = p1.w + q1.w + coef1 * hd1.w;

        if (have_ovf > 0) {
            *reinterpret_cast<float4*>(acc_u + (size_t)bin0 * HID + lane * 4) = s0;
            *reinterpret_cast<float4*>(acc_u + (size_t)bin1 * HID + lane * 4) = s1;
        }

        float4 e0, e1;
        e0.x = elu1(s0.x); e0.y = elu1(s0.y); e0.z = elu1(s0.z); e0.w = elu1(s0.w);
        e1.x = elu1(s1.x); e1.y = elu1(s1.y); e1.z = elu1(s1.z); e1.w = elu1(s1.w);
        *reinterpret_cast<float4*>(&sRow[wid][0][lane * 4]) = e0;
        *reinterpret_cast<float4*>(&sRow[wid][1][lane * 4]) = e1;
        __syncwarp();

        float4 o = bv;
        const float* row = &sRow[wid][b][0];
#pragma unroll
        for (int k4 = 0; k4 < HID / 4; k4++) {
            float4 rv = *reinterpret_cast<const float4*>(row + k4 * 4);
            float4 w0 = *reinterpret_cast<const float4*>(&Ws[k4 * 4 + 0][j0]);
            float4 w1 = *reinterpret_cast<const float4*>(&Ws[k4 * 4 + 1][j0]);
            float4 w2 = *reinterpret_cast<const float4*>(&Ws[k4 * 4 + 2][j0]);
            float4 w3 = *reinterpret_cast<const float4*>(&Ws[k4 * 4 + 3][j0]);
            o.x += rv.x * w0.x + rv.y * w1.x + rv.z * w2.x + rv.w * w3.x;
            o.y += rv.x * w0.y + rv.y * w1.y + rv.z * w2.y + rv.w * w3.y;
            o.z += rv.x * w0.z + rv.y * w1.z + rv.z * w2.z + rv.w * w3.z;
            o.w += rv.x * w0.w + rv.y * w1.w + rv.z * w2.w + rv.w * w3.w;
        }
        *reinterpret_cast<float4*>(out + (size_t)(bin0 + b) * OUT_DIM + j0) = o;
        __syncwarp();
    }
}

// ---------------------------------------------------------------------------
// ITEM bins (unchanged): single relation, elu -> out_i.
// ---------------------------------------------------------------------------
__global__ __launch_bounds__(256) void bin_acc_item_kernel(
    const float* __restrict__ h,
    const float* __restrict__ al_ui, const float* __restrict__ ar_ui,
    float* __restrict__ out_i)
{
    int w = blockIdx.x * 8 + (threadIdx.x >> 5);
    if (w >= NI / 2) return;
    int lane = threadIdx.x & 31;
    int bin0 = NU + 2 * w;
    int bin1 = bin0 + 1;

    const float al = __ldg(al_ui);
    const float ar = __ldg(ar_ui);

    int n0 = __ldg(&g_cnt[bin0]); if (n0 > BCAP) n0 = BCAP;
    int n1 = __ldg(&g_cnt[bin1]); if (n1 > BCAP) n1 = BCAP;
    if (lane < 2) g_cnt[bin0 + lane] = 0;

    uint32_t ro0 = (lane < n0) ? __ldg(&g_bucket[(size_t)bin0 * BCAP + lane]) : 0u;
    uint32_t ro1 = (lane < n1) ? __ldg(&g_bucket[(size_t)bin1 * BCAP + lane]) : 0u;

    const float4* h4 = reinterpret_cast<const float4*>(h);
    float4 p0 = make_float4(0.f, 0.f, 0.f, 0.f);
    float4 q0 = make_float4(0.f, 0.f, 0.f, 0.f);
    float4 p1 = make_float4(0.f, 0.f, 0.f, 0.f);
    float4 q1 = make_float4(0.f, 0.f, 0.f, 0.f);

    int nmax = n0 > n1 ? n0 : n1;
    for (int j = 0; j < nmax; j += 2) {
        uint32_t rA0 = __shfl_sync(0xFFFFFFFFu, ro0, j);
        uint32_t rB0 = __shfl_sync(0xFFFFFFFFu, ro0, (j + 1) & 31);
        uint32_t rA1 = __shfl_sync(0xFFFFFFFFu, ro1, j);
        uint32_t rB1 = __shfl_sync(0xFFFFFFFFu, ro1, (j + 1) & 31);
        float aA0 = (j     < n0) ? al : 0.f; if (j     >= n0) rA0 = 0;
        float aB0 = (j + 1 < n0) ? al : 0.f; if (j + 1 >= n0) rB0 = 0;
        float aA1 = (j     < n1) ? al : 0.f; if (j     >= n1) rA1 = 0;
        float aB1 = (j + 1 < n1) ? al : 0.f; if (j + 1 >= n1) rB1 = 0;
        float4 vA0 = __ldg(h4 + (size_t)rA0 * 32 + lane);
        float4 vB0 = __ldg(h4 + (size_t)rB0 * 32 + lane);
        float4 vA1 = __ldg(h4 + (size_t)rA1 * 32 + lane);
        float4 vB1 = __ldg(h4 + (size_t)rB1 * 32 + lane);
        p0.x += aA0 * vA0.x; p0.y += aA0 * vA0.y; p0.z += aA0 * vA0.z; p0.w += aA0 * vA0.w;
        q0.x += aB0 * vB0.x; q0.y += aB0 * vB0.y; q0.z += aB0 * vB0.z; q0.w += aB0 * vB0.w;
        p1.x += aA1 * vA1.x; p1.y += aA1 * vA1.y; p1.z += aA1 * vA1.z; p1.w += aA1 * vA1.w;
        q1.x += aB1 * vB1.x; q1.y += aB1 * vB1.y; q1.z += aB1 * vB1.z; q1.w += aB1 * vB1.w;
    }

    float coef0 = (float)n0 * ar;
    float coef1 = (float)n1 * ar;
    float4 hd0 = __ldg(h4 + (size_t)bin0 * 32 + lane);
    float4 hd1 = __ldg(h4 + (size_t)bin1 * 32 + lane);
    float4 s0, s1;
    s0.x = elu1(p0.x + q0.x + coef0 * hd0.x);
    s0.y = elu1(p0.y + q0.y + coef0 * hd0.y);
    s0.z = elu1(p0.z + q0.z + coef0 * hd0.z);
    s0.w = elu1(p0.w + q0.w + coef0 * hd0.w);
    s1.x = elu1(p1.x + q1.x + coef1 * hd1.x);
    s1.y = elu1(p1.y + q1.y + coef1 * hd1.y);
    s1.z = elu1(p1.z + q1.z + coef1 * hd1.z);
    s1.w = elu1(p1.w + q1.w + coef1 * hd1.w);

    *reinterpret_cast<float4*>(out_i + (size_t)(bin0 - NU) * HID + lane * 4) = s0;
    *reinterpret_cast<float4*>(out_i + (size_t)(bin1 - NU) * HID + lane * 4) = s1;
}

// ---------------------------------------------------------------------------
// Overflow + repair, single block (cold path; exits immediately when nov==0).
// ---------------------------------------------------------------------------
__global__ __launch_bounds__(256) void ovf_repair_kernel(
    const float* __restrict__ h,
    const float* __restrict__ al_uu, const float* __restrict__ ar_uu,
    const float* __restrict__ al_iu, const float* __restrict__ ar_iu,
    float* __restrict__ acc_u,
    const float* __restrict__ Wout, const float* __restrict__ bout,
    float* __restrict__ out)
{
    int nov = g_ovfn;
    if (nov > OVF_CAP) nov = OVF_CAP;
    if (nov <= 0) return;
    int lane = threadIdx.x & 31;
    int w = threadIdx.x >> 5;

    // Phase 1: apply overflow messages (one warp per entry)
    for (int idx = w; idx < nov; idx += 8) {
        uint2 ov = g_ovf[idx];
        int bin = (int)ov.x;
        if (bin >= NU) continue;
        uint32_t v = ov.y;
        uint32_t src = v & 0x7FFFFFFFu;
        float al, ar;
        size_t row;
        if (v & 0x80000000u) { al = __ldg(al_iu); ar = __ldg(ar_iu); row = (size_t)NU + src; }
        else                 { al = __ldg(al_uu); ar = __ldg(ar_uu); row = src; }
        float4 hs = *reinterpret_cast<const float4*>(h + row * HID + lane * 4);
        float4 hd = *reinterpret_cast<const float4*>(h + (size_t)bin * HID + lane * 4);
        float* dst = acc_u + (size_t)bin * HID + lane * 4;
        atomicAdd(dst + 0, al * hs.x + ar * hd.x);
        atomicAdd(dst + 1, al * hs.y + ar * hd.y);
        atomicAdd(dst + 2, al * hs.z + ar * hd.z);
        atomicAdd(dst + 3, al * hs.w + ar * hd.w);
    }
    __syncthreads();

    // Phase 2: recompute out rows for overflowed bins (idempotent per bin)
    for (int i = w; i < nov; i += 8) {
        int bin = (int)g_ovf[i].x;
        if (bin >= NU) continue;
        float o0 = __ldg(&bout[lane * 2]);
        float o1 = __ldg(&bout[lane * 2 + 1]);
        for (int k = 0; k < HID; k++) {
            float rv = elu1(ldcg(acc_u + (size_t)bin * HID + k));
            o0 += rv * __ldg(&Wout[k * OUT_DIM + lane * 2]);
            o1 += rv * __ldg(&Wout[k * OUT_DIM + lane * 2 + 1]);
        }
        out[(size_t)bin * OUT_DIM + lane * 2]     = o0;
        out[(size_t)bin * OUT_DIM + lane * 2 + 1] = o1;
    }
    __syncthreads();
    if (threadIdx.x == 0) g_ovfn = 0;
}

// ---------------------------------------------------------------------------
// Launch: fork/join DAG.
//   main: prep -> proj -> [join fill] -> bin_acc_user(+GEMM) -> ovf_repair
//   s1:   fill (forked at entry)
//   s2:   bin_acc_item (waits on ev_mid = proj+fill), joined at end
// Issue order: fill(1) prep(2) proj(3) bin_acc_user(4) item(5) ovf_repair(6)
// ---------------------------------------------------------------------------
extern "C" void kernel_launch(void* const* d_in, const int* in_sizes, int n_in,
                              void* d_out, int out_size)
{
    const float* xu    = (const float*)d_in[0];
    const float* xi    = (const float*)d_in[1];
    const float* Wp    = (const float*)d_in[2];
    const float* bp    = (const float*)d_in[3];
    const float* al_uu = (const float*)d_in[4];
    const float* ar_uu = (const float*)d_in[5];
    const float* al_iu = (const float*)d_in[6];
    const float* ar_iu = (const float*)d_in[7];
    const float* al_ui = (const float*)d_in[8];
    const float* ar_ui = (const float*)d_in[9];
    const float* Wo    = (const float*)d_in[10];
    const float* bo    = (const float*)d_in[11];
    const int*   e_uu  = (const int*)d_in[12];
    const int*   e_iu  = (const int*)d_in[13];
    const int*   e_ui  = (const int*)d_in[14];
    const int E_uu = in_sizes[12] / 2;
    const int E_iu = in_sizes[13] / 2;
    const int E_ui = in_sizes[14] / 2;

    float*    h;   cudaGetSymbolAddress((void**)&h,   g_h);
    float*    acc; cudaGetSymbolAddress((void**)&acc, g_acc);
    uint32_t* Wt;  cudaGetSymbolAddress((void**)&Wt,  g_Wt);

    float* out_u = (float*)d_out;
    float* out_i = out_u + (size_t)NU * OUT_DIM;

    static cudaStream_t s1 = nullptr, s2 = nullptr;
    static cudaEvent_t ev_fork, ev_fill, ev_mid, ev_item;
    if (s1 == nullptr) {
        cudaStreamCreateWithFlags(&s1, cudaStreamNonBlocking);
        cudaStreamCreateWithFlags(&s2, cudaStreamNonBlocking);
        cudaEventCreateWithFlags(&ev_fork, cudaEventDisableTiming);
        cudaEventCreateWithFlags(&ev_fill, cudaEventDisableTiming);
        cudaEventCreateWithFlags(&ev_mid, cudaEventDisableTiming);
        cudaEventCreateWithFlags(&ev_item, cudaEventDisableTiming);
        cudaFuncSetAttribute(proj_mma_kernel,
                             cudaFuncAttributeMaxDynamicSharedMemorySize, PROJ_SMEM);
    }

    int totE = E_uu + E_iu + E_ui;

    // Fork fill onto s1
    cudaEventRecord(ev_fork, 0);
    cudaStreamWaitEvent(s1, ev_fork, 0);
    fill_bucket_kernel<<<(totE + 255) / 256, 256, 0, s1>>>(
        (const int2*)e_uu, E_uu, (const int2*)e_iu, E_iu, (const int2*)e_ui, E_ui);
    cudaEventRecord(ev_fill, s1);

    // Main: prep -> proj (concurrent with fill)
    prep_kernel<<<(IN_DIM * HID + 255) / 256, 256>>>(Wp, Wt);
    proj_mma_kernel<<<(M_TOT + BM - 1) / BM, 256, PROJ_SMEM>>>(xu, xi, Wt, bp, h);

    // Join fill; mark the point both branches may start from
    cudaStreamWaitEvent(0, ev_fill, 0);
    cudaEventRecord(ev_mid, 0);

    // Main: user branch (fused GEMM, grid-strided)
    bin_acc_user_kernel<<<NU / (16 * UGRP), 256>>>(
        h, al_uu, ar_uu, al_iu, ar_iu, Wo, bo, acc, out_u);

    // Side: item branch, concurrent with user branch
    cudaStreamWaitEvent(s2, ev_mid, 0);
    bin_acc_item_kernel<<<(NI / 2 + 7) / 8, 256, 0, s2>>>(h, al_ui, ar_ui, out_i);
    cudaEventRecord(ev_item, s2);

    // Cold-path overflow handling (after user branch on main)
    ovf_repair_kernel<<<1, 256>>>(h, al_uu, ar_uu, al_iu, ar_iu, acc, Wo, bo, out_u);

    // Join item branch before the harness consumes d_out
    cudaStreamWaitEvent(0, ev_item, 0);
}

// round 14
// speedup vs baseline: 1.1189x; 1.1189x over previous
#include <cuda_runtime.h>
#include <math.h>
#include <stdint.h>

// Problem constants
#define NU      50000
#define NI      50000
#define M_TOT   100000
#define IN_DIM  256
#define HID     128
#define OUT_DIM 64
#define NBIN    (NU + NI)
#define BCAP    32
#define OVF_CAP 8192

// ---------------------------------------------------------------------------
// Device scratch
// ---------------------------------------------------------------------------
__device__ float    g_h[(size_t)M_TOT * HID];
__device__ float    g_acc[(size_t)NU * HID];       // only written on overflow
__device__ uint32_t g_Wt[IN_DIM * HID];            // W in tf32 bits, B-FRAGMENT layout
__device__ int      g_cnt[NBIN];                   // zero-init; re-zeroed by bin_acc
__device__ uint32_t g_bucket[(size_t)NBIN * BCAP];
__device__ int      g_ovfn;                        // reset by ovf_repair
__device__ uint2    g_ovf[OVF_CAP];

__device__ __forceinline__ float elu1(float x) { return x > 0.f ? x : expm1f(x); }

__device__ __forceinline__ uint32_t smem_u32(const void* p) {
    uint32_t a;
    asm("{ .reg .u64 t; cvta.to.shared.u64 t, %1; cvt.u32.u64 %0, t; }" : "=r"(a) : "l"(p));
    return a;
}

__device__ __forceinline__ void cp_async16(uint32_t dst_smem, const void* src) {
    asm volatile("cp.async.cg.shared.global [%0], [%1], 16;"
                 :: "r"(dst_smem), "l"(src) : "memory");
}
#define CP_COMMIT() asm volatile("cp.async.commit_group;" ::: "memory")

__device__ __forceinline__ uint32_t f2tf32(float v) {
    uint32_t t;
    asm("cvt.rna.tf32.f32 %0, %1;" : "=r"(t) : "f"(v));
    return t;
}

__device__ __forceinline__ float ldcg(const float* p) {
    float v;
    asm volatile("ld.global.cg.f32 %0, [%1];" : "=f"(v) : "l"(p));
    return v;
}

__device__ __forceinline__ void mma_tf32(float& d0, float& d1, float& d2, float& d3,
                                         uint32_t a0, uint32_t a1, uint32_t a2, uint32_t a3,
                                         uint32_t b0, uint32_t b1) {
    asm volatile(
        "mma.sync.aligned.m16n8k8.row.col.f32.tf32.tf32.f32 "
        "{%0,%1,%2,%3}, {%4,%5,%6,%7}, {%8,%9}, {%0,%1,%2,%3};"
        : "+f"(d0), "+f"(d1), "+f"(d2), "+f"(d3)
        : "r"(a0), "r"(a1), "r"(a2), "r"(a3), "r"(b0), "r"(b1));
}

// ---------------------------------------------------------------------------
// prep: convert W[k][n] -> tf32 bits in B-FRAGMENT layout (as R9).
// ---------------------------------------------------------------------------
__global__ void prep_kernel(const float* __restrict__ W, uint32_t* __restrict__ Wt) {
    int i = blockIdx.x * 256 + threadIdx.x;
    if (i >= IN_DIM * HID) return;
    int k = i >> 7;
    int n = i & 127;
    int c    = k >> 5;
    int ks   = (k >> 3) & 3;
    int slot = (k >> 2) & 1;
    int tig  = k & 3;
    int wn   = n >> 5;
    int nt   = (n >> 3) & 3;
    int gid  = n & 7;
    int lane = gid * 4 + tig;
    int idx  = c * 4096 + (((ks * 4 + wn) * 4 + nt) * 32 + lane) * 2 + slot;
    Wt[idx] = f2tf32(W[i]);
}

// ---------------------------------------------------------------------------
// Projection via mma.sync tf32, fragment-major smem (unchanged from R9).
// ---------------------------------------------------------------------------
#define KC       32
#define NCHUNK   (IN_DIM / KC)
#define BM       64
#define ASF_W    2112
#define BSF_W    4096
#define PROJ_SMEM ((2 * ASF_W + 2 * BSF_W) * 4)   // 49664 bytes

__device__ __forceinline__ void ldA_regs(const float* __restrict__ xu,
                                         const float* __restrict__ xi,
                                         int m0, int c, int tid, float4* r) {
#pragma unroll
    for (int L = 0; L < 2; L++) {
        int i = tid + L * 256;
        int row = i >> 3;
        int seg = i & 7;
        int gr = m0 + row;
        if (gr >= M_TOT) gr = M_TOT - 1;
        const float* src = (gr < NU) ? (xu + (size_t)gr * IN_DIM)
                                     : (xi + (size_t)(gr - NU) * IN_DIM);
        r[L] = *reinterpret_cast<const float4*>(src + c * KC + seg * 4);
    }
}

__device__ __forceinline__ void stA_smem(uint32_t* __restrict__ As, int tid,
                                         const float4* r) {
#pragma unroll
    for (int L = 0; L < 2; L++) {
        int i = tid + L * 256;
        int row = i >> 3;
        int seg = i & 7;
        int rg    = row >> 4;
        int gid   = row & 7;
        int slotb = (row >> 3) & 1;
        int ks    = seg >> 1;
        int slot  = slotb + 2 * (seg & 1);
        uint32_t* base = As + (rg * 4 + ks) * 132 + gid * 16 + slot;
        base[0]  = f2tf32(r[L].x);
        base[4]  = f2tf32(r[L].y);
        base[8]  = f2tf32(r[L].z);
        base[12] = f2tf32(r[L].w);
    }
}

__device__ __forceinline__ void ldB_cpasync(uint32_t sB, const uint32_t* __restrict__ Wt,
                                            int c, int tid) {
#pragma unroll
    for (int L = 0; L < 4; L++) {
        int i = tid + L * 256;
        cp_async16(sB + i * 16, Wt + (size_t)c * 4096 + i * 4);
    }
    CP_COMMIT();
}

__global__ __launch_bounds__(256, 3) void proj_mma_kernel(
    const float* __restrict__ xu, const float* __restrict__ xi,
    const uint32_t* __restrict__ Wt, const float* __restrict__ bias,
    float* __restrict__ h)
{
    extern __shared__ uint32_t smw[];
    uint32_t sb = smem_u32(smw);
    const int tid  = threadIdx.x;
    const int wid  = tid >> 5;
    const int lane = tid & 31;
    const int gid  = lane >> 2;
    const int tig  = lane & 3;
    const int wm   = wid >> 2;
    const int wn   = wid & 3;
    const int m0   = blockIdx.x * BM;

    float d[2][4][4];
#pragma unroll
    for (int i = 0; i < 2; i++)
#pragma unroll
        for (int j = 0; j < 4; j++)
#pragma unroll
            for (int q = 0; q < 4; q++) d[i][j][q] = 0.f;

    float4 rA[2];
    ldA_regs(xu, xi, m0, 0, tid, rA);
    ldB_cpasync(sb + (2 * ASF_W + 0 * BSF_W) * 4, Wt, 0, tid);
    ldB_cpasync(sb + (2 * ASF_W + 1 * BSF_W) * 4, Wt, 1, tid);

    for (int c = 0; c < NCHUNK; c++) {
        int s = c & 1;
        uint32_t* As = smw + s * ASF_W;
        const uint32_t* Bs = smw + 2 * ASF_W + s * BSF_W;

        stA_smem(As, tid, rA);
        if (c + 1 < NCHUNK) ldA_regs(xu, xi, m0, c + 1, tid, rA);

        if (c < NCHUNK - 1) asm volatile("cp.async.wait_group 1;" ::: "memory");
        else                asm volatile("cp.async.wait_group 0;" ::: "memory");
        __syncthreads();

#pragma unroll
        for (int ks = 0; ks < KC / 8; ks++) {
            uint32_t a[2][4];
#pragma unroll
            for (int mt = 0; mt < 2; mt++) {
                int rg = wm * 2 + mt;
                uint4 av = *reinterpret_cast<const uint4*>(
                    As + (rg * 4 + ks) * 132 + lane * 4);
                a[mt][0] = av.x; a[mt][1] = av.y; a[mt][2] = av.z; a[mt][3] = av.w;
            }
            uint32_t b[4][2];
#pragma unroll
            for (int nt = 0; nt < 4; nt++) {
                uint2 bv = *reinterpret_cast<const uint2*>(
                    Bs + (((ks * 4 + wn) * 4 + nt) * 32 + lane) * 2);
                b[nt][0] = bv.x; b[nt][1] = bv.y;
            }
#pragma unroll
            for (int mt = 0; mt < 2; mt++)
#pragma unroll
                for (int nt = 0; nt < 4; nt++)
                    mma_tf32(d[mt][nt][0], d[mt][nt][1], d[mt][nt][2], d[mt][nt][3],
                             a[mt][0], a[mt][1], a[mt][2], a[mt][3],
                             b[nt][0], b[nt][1]);
        }
        __syncthreads();
        if (c + 2 < NCHUNK)
            ldB_cpasync(sb + (2 * ASF_W + s * BSF_W) * 4, Wt, c + 2, tid);
    }

#pragma unroll
    for (int mt = 0; mt < 2; mt++) {
        int row0 = m0 + wm * 32 + mt * 16 + gid;
        int row1 = row0 + 8;
#pragma unroll
        for (int nt = 0; nt < 4; nt++) {
            int col = wn * 32 + nt * 8 + tig * 2;
            float2 bv = *reinterpret_cast<const float2*>(bias + col);
            if (row0 < M_TOT) {
                float2 v = make_float2(d[mt][nt][0] + bv.x, d[mt][nt][1] + bv.y);
                *reinterpret_cast<float2*>(h + (size_t)row0 * HID + col) = v;
            }
            if (row1 < M_TOT) {
                float2 v = make_float2(d[mt][nt][2] + bv.x, d[mt][nt][3] + bv.y);
                *reinterpret_cast<float2*>(h + (size_t)row1 * HID + col) = v;
            }
        }
    }
}

// ---------------------------------------------------------------------------
// Fill destination buckets from the three edge lists.
// ---------------------------------------------------------------------------
__global__ void fill_bucket_kernel(const int2* __restrict__ e_uu, int Euu,
                                   const int2* __restrict__ e_iu, int Eiu,
                                   const int2* __restrict__ e_ui, int Eui) {
    int e = blockIdx.x * 256 + threadIdx.x;
    int tot = Euu + Eiu + Eui;
    if (e >= tot) return;
    int2 ed;
    int bin;
    uint32_t val;
    if (e < Euu) {
        ed = __ldg(&e_uu[e]);             bin = ed.y;      val = (uint32_t)ed.x;
    } else if (e < Euu + Eiu) {
        ed = __ldg(&e_iu[e - Euu]);       bin = ed.y;      val = (uint32_t)ed.x | 0x80000000u;
    } else {
        ed = __ldg(&e_ui[e - Euu - Eiu]); bin = NU + ed.y; val = (uint32_t)ed.x;
    }
    int pos = atomicAdd(&g_cnt[bin], 1);
    if (pos < BCAP) {
        g_bucket[(size_t)bin * BCAP + pos] = val;
    } else {
        int o = atomicAdd(&g_ovfn, 1);
        if (o < OVF_CAP) g_ovf[o] = make_uint2((uint32_t)bin, val);
    }
}

// ---------------------------------------------------------------------------
// USER bins, FUSED with output GEMM (R11 shape: 16 bins/block, 3125 blocks).
// ---------------------------------------------------------------------------
__global__ __launch_bounds__(256) void bin_acc_user_kernel(
    const float* __restrict__ h,
    const float* __restrict__ al_uu, const float* __restrict__ ar_uu,
    const float* __restrict__ al_iu, const float* __restrict__ ar_iu,
    const float* __restrict__ Wout, const float* __restrict__ bout,
    float* __restrict__ acc_u, float* __restrict__ out)
{
    __shared__ float Ws[HID][OUT_DIM];      // 32 KB
    __shared__ float sRow[8][2][HID];       // 8 KB

    const int tid  = threadIdx.x;
    const int wid  = tid >> 5;
    const int lane = tid & 31;
    const int have_ovf = g_ovfn;

#pragma unroll
    for (int L = 0; L < 8; L++) {
        int idx = tid + L * 256;
        reinterpret_cast<float4*>(&Ws[0][0])[idx] =
            reinterpret_cast<const float4*>(Wout)[idx];
    }
    __syncthreads();

    int bin0 = blockIdx.x * 16 + 2 * wid;   // NU = 3125 * 16, exact
    int bin1 = bin0 + 1;

    int n0 = __ldg(&g_cnt[bin0]); if (n0 > BCAP) n0 = BCAP;
    int n1 = __ldg(&g_cnt[bin1]); if (n1 > BCAP) n1 = BCAP;
    if (lane < 2) g_cnt[bin0 + lane] = 0;

    float al0 = 0.f, ar0 = 0.f, al1 = 0.f, ar1 = 0.f;
    uint32_t ro0 = 0, ro1 = 0;
    if (lane < n0) {
        uint32_t v = __ldg(&g_bucket[(size_t)bin0 * BCAP + lane]);
        uint32_t src = v & 0x7FFFFFFFu;
        if (v & 0x80000000u) { al0 = __ldg(al_iu); ar0 = __ldg(ar_iu); ro0 = NU + src; }
        else                 { al0 = __ldg(al_uu); ar0 = __ldg(ar_uu); ro0 = src; }
    }
    if (lane < n1) {
        uint32_t v = __ldg(&g_bucket[(size_t)bin1 * BCAP + lane]);
        uint32_t src = v & 0x7FFFFFFFu;
        if (v & 0x80000000u) { al1 = __ldg(al_iu); ar1 = __ldg(ar_iu); ro1 = NU + src; }
        else                 { al1 = __ldg(al_uu); ar1 = __ldg(ar_uu); ro1 = src; }
    }

    float coef0 = ar0, coef1 = ar1;
#pragma unroll
    for (int o = 16; o; o >>= 1) {
        coef0 += __shfl_xor_sync(0xFFFFFFFFu, coef0, o);
        coef1 += __shfl_xor_sync(0xFFFFFFFFu, coef1, o);
    }

    const float4* h4 = reinterpret_cast<const float4*>(h);
    float4 p0 = make_float4(0.f, 0.f, 0.f, 0.f);
    float4 q0 = make_float4(0.f, 0.f, 0.f, 0.f);
    float4 p1 = make_float4(0.f, 0.f, 0.f, 0.f);
    float4 q1 = make_float4(0.f, 0.f, 0.f, 0.f);

    int nmax = n0 > n1 ? n0 : n1;
    for (int j = 0; j < nmax; j += 2) {
        uint32_t rA0 = __shfl_sync(0xFFFFFFFFu, ro0, j);
        float    aA0 = __shfl_sync(0xFFFFFFFFu, al0, j);
        uint32_t rB0 = __shfl_sync(0xFFFFFFFFu, ro0, (j + 1) & 31);
        float    aB0 = __shfl_sync(0xFFFFFFFFu, al0, (j + 1) & 31);
        uint32_t rA1 = __shfl_sync(0xFFFFFFFFu, ro1, j);
        float    aA1 = __shfl_sync(0xFFFFFFFFu, al1, j);
        uint32_t rB1 = __shfl_sync(0xFFFFFFFFu, ro1, (j + 1) & 31);
        float    aB1 = __shfl_sync(0xFFFFFFFFu, al1, (j + 1) & 31);
        if (j     >= n0) { aA0 = 0.f; rA0 = 0; }
        if (j + 1 >= n0) { aB0 = 0.f; rB0 = 0; }
        if (j     >= n1) { aA1 = 0.f; rA1 = 0; }
        if (j + 1 >= n1) { aB1 = 0.f; rB1 = 0; }
        float4 vA0 = __ldg(h4 + (size_t)rA0 * 32 + lane);
        float4 vB0 = __ldg(h4 + (size_t)rB0 * 32 + lane);
        float4 vA1 = __ldg(h4 + (size_t)rA1 * 32 + lane);
        float4 vB1 = __ldg(h4 + (size_t)rB1 * 32 + lane);
        p0.x += aA0 * vA0.x; p0.y += aA0 * vA0.y; p0.z += aA0 * vA0.z; p0.w += aA0 * vA0.w;
        q0.x += aB0 * vB0.x; q0.y += aB0 * vB0.y; q0.z += aB0 * vB0.z; q0.w += aB0 * vB0.w;
        p1.x += aA1 * vA1.x; p1.y += aA1 * vA1.y; p1.z += aA1 * vA1.z; p1.w += aA1 * vA1.w;
        q1.x += aB1 * vB1.x; q1.y += aB1 * vB1.y; q1.z += aB1 * vB1.z; q1.w += aB1 * vB1.w;
    }

    float4 hd0 = __ldg(h4 + (size_t)bin0 * 32 + lane);
    float4 hd1 = __ldg(h4 + (size_t)bin1 * 32 + lane);
    float4 s0, s1;
    s0.x = p0.x + q0.x + coef0 * hd0.x;
    s0.y = p0.y + q0.y + coef0 * hd0.y;
    s0.z = p0.z + q0.z + coef0 * hd0.z;
    s0.w = p0.w + q0.w + coef0 * hd0.w;
    s1.x = p1.x + q1.x + coef1 * hd1.x;
    s1.y = p1.y + q1.y + coef1 * hd1.y;
    s1.z = p1.z + q1.z + coef1 * hd1.z;
    s1.w = p1.w + q1.w + coef1 * hd1.w;

    if (have_ovf > 0) {
        *reinterpret_cast<float4*>(acc_u + (size_t)bin0 * HID + lane * 4) = s0;
        *reinterpret_cast<float4*>(acc_u + (size_t)bin1 * HID + lane * 4) = s1;
    }

    float4 e0, e1;
    e0.x = elu1(s0.x); e0.y = elu1(s0.y); e0.z = elu1(s0.z); e0.w = elu1(s0.w);
    e1.x = elu1(s1.x); e1.y = elu1(s1.y); e1.z = elu1(s1.z); e1.w = elu1(s1.w);
    *reinterpret_cast<float4*>(&sRow[wid][0][lane * 4]) = e0;
    *reinterpret_cast<float4*>(&sRow[wid][1][lane * 4]) = e1;
    __syncwarp();

    const int b  = lane >> 4;
    const int j0 = (lane & 15) * 4;
    float4 o = *reinterpret_cast<const float4*>(bout + j0);
    const float* row = &sRow[wid][b][0];
#pragma unroll
    for (int k4 = 0; k4 < HID / 4; k4++) {
        float4 rv = *reinterpret_cast<const float4*>(row + k4 * 4);
        float4 w0 = *reinterpret_cast<const float4*>(&Ws[k4 * 4 + 0][j0]);
        float4 w1 = *reinterpret_cast<const float4*>(&Ws[k4 * 4 + 1][j0]);
        float4 w2 = *reinterpret_cast<const float4*>(&Ws[k4 * 4 + 2][j0]);
        float4 w3 = *reinterpret_cast<const float4*>(&Ws[k4 * 4 + 3][j0]);
        o.x += rv.x * w0.x + rv.y * w1.x + rv.z * w2.x + rv.w * w3.x;
        o.y += rv.x * w0.y + rv.y * w1.y + rv.z * w2.y + rv.w * w3.y;
        o.z += rv.x * w0.z + rv.y * w1.z + rv.z * w2.z + rv.w * w3.z;
        o.w += rv.x * w0.w + rv.y * w1.w + rv.z * w2.w + rv.w * w3.w;
    }
    *reinterpret_cast<float4*>(out + (size_t)(bin0 + b) * OUT_DIM + j0) = o;
}

// ---------------------------------------------------------------------------
// ITEM bins: single relation, elu -> out_i.
// ---------------------------------------------------------------------------
__global__ __launch_bounds__(256) void bin_acc_item_kernel(
    const float* __restrict__ h,
    const float* __restrict__ al_ui, const float* __restrict__ ar_ui,
    float* __restrict__ out_i)
{
    int w = blockIdx.x * 8 + (threadIdx.x >> 5);
    if (w >= NI / 2) return;
    int lane = threadIdx.x & 31;
    int bin0 = NU + 2 * w;
    int bin1 = bin0 + 1;

    const float al = __ldg(al_ui);
    const float ar = __ldg(ar_ui);

    int n0 = __ldg(&g_cnt[bin0]); if (n0 > BCAP) n0 = BCAP;
    int n1 = __ldg(&g_cnt[bin1]); if (n1 > BCAP) n1 = BCAP;
    if (lane < 2) g_cnt[bin0 + lane] = 0;

    uint32_t ro0 = (lane < n0) ? __ldg(&g_bucket[(size_t)bin0 * BCAP + lane]) : 0u;
    uint32_t ro1 = (lane < n1) ? __ldg(&g_bucket[(size_t)bin1 * BCAP + lane]) : 0u;

    const float4* h4 = reinterpret_cast<const float4*>(h);
    float4 p0 = make_float4(0.f, 0.f, 0.f, 0.f);
    float4 q0 = make_float4(0.f, 0.f, 0.f, 0.f);
    float4 p1 = make_float4(0.f, 0.f, 0.f, 0.f);
    float4 q1 = make_float4(0.f, 0.f, 0.f, 0.f);

    int nmax = n0 > n1 ? n0 : n1;
    for (int j = 0; j < nmax; j += 2) {
        uint32_t rA0 = __shfl_sync(0xFFFFFFFFu, ro0, j);
        uint32_t rB0 = __shfl_sync(0xFFFFFFFFu, ro0, (j + 1) & 31);
        uint32_t rA1 = __shfl_sync(0xFFFFFFFFu, ro1, j);
        uint32_t rB1 = __shfl_sync(0xFFFFFFFFu, ro1, (j + 1) & 31);
        float aA0 = (j     < n0) ? al : 0.f; if (j     >= n0) rA0 = 0;
        float aB0 = (j + 1 < n0) ? al : 0.f; if (j + 1 >= n0) rB0 = 0;
        float aA1 = (j     < n1) ? al : 0.f; if (j     >= n1) rA1 = 0;
        float aB1 = (j + 1 < n1) ? al : 0.f; if (j + 1 >= n1) rB1 = 0;
        float4 vA0 = __ldg(h4 + (size_t)rA0 * 32 + lane);
        float4 vB0 = __ldg(h4 + (size_t)rB0 * 32 + lane);
        float4 vA1 = __ldg(h4 + (size_t)rA1 * 32 + lane);
        float4 vB1 = __ldg(h4 + (size_t)rB1 * 32 + lane);
        p0.x += aA0 * vA0.x; p0.y += aA0 * vA0.y; p0.z += aA0 * vA0.z; p0.w += aA0 * vA0.w;
        q0.x += aB0 * vB0.x; q0.y += aB0 * vB0.y; q0.z += aB0 * vB0.z; q0.w += aB0 * vB0.w;
        p1.x += aA1 * vA1.x; p1.y += aA1 * vA1.y; p1.z += aA1 * vA1.z; p1.w += aA1 * vA1.w;
        q1.x += aB1 * vB1.x; q1.y += aB1 * vB1.y; q1.z += aB1 * vB1.z; q1.w += aB1 * vB1.w;
    }

    float coef0 = (float)n0 * ar;
    float coef1 = (float)n1 * ar;
    float4 hd0 = __ldg(h4 + (size_t)bin0 * 32 + lane);
    float4 hd1 = __ldg(h4 + (size_t)bin1 * 32 + lane);
    float4 s0, s1;
    s0.x = elu1(p0.x + q0.x + coef0 * hd0.x);
    s0.y = elu1(p0.y + q0.y + coef0 * hd0.y);
    s0.z = elu1(p0.z + q0.z + coef0 * hd0.z);
    s0.w = elu1(p0.w + q0.w + coef0 * hd0.w);
    s1.x = elu1(p1.x + q1.x + coef1 * hd1.x);
    s1.y = elu1(p1.y + q1.y + coef1 * hd1.y);
    s1.z = elu1(p1.z + q1.z + coef1 * hd1.z);
    s1.w = elu1(p1.w + q1.w + coef1 * hd1.w);

    *reinterpret_cast<float4*>(out_i + (size_t)(bin0 - NU) * HID + lane * 4) = s0;
    *reinterpret_cast<float4*>(out_i + (size_t)(bin1 - NU) * HID + lane * 4) = s1;
}

// ---------------------------------------------------------------------------
// Overflow + repair, single block (cold path; exits immediately when nov==0).
// ---------------------------------------------------------------------------
__global__ __launch_bounds__(256) void ovf_repair_kernel(
    const float* __restrict__ h,
    const float* __restrict__ al_uu, const float* __restrict__ ar_uu,
    const float* __restrict__ al_iu, const float* __restrict__ ar_iu,
    float* __restrict__ acc_u,
    const float* __restrict__ Wout, const float* __restrict__ bout,
    float* __restrict__ out)
{
    int nov = g_ovfn;
    if (nov > OVF_CAP) nov = OVF_CAP;
    if (nov <= 0) return;
    int lane = threadIdx.x & 31;
    int w = threadIdx.x >> 5;

    // Phase 1: apply overflow messages (one warp per entry)
    for (int idx = w; idx < nov; idx += 8) {
        uint2 ov = g_ovf[idx];
        int bin = (int)ov.x;
        if (bin >= NU) continue;
        uint32_t v = ov.y;
        uint32_t src = v & 0x7FFFFFFFu;
        float al, ar;
        size_t row;
        if (v & 0x80000000u) { al = __ldg(al_iu); ar = __ldg(ar_iu); row = (size_t)NU + src; }
        else                 { al = __ldg(al_uu); ar = __ldg(ar_uu); row = src; }
        float4 hs = *reinterpret_cast<const float4*>(h + row * HID + lane * 4);
        float4 hd = *reinterpret_cast<const float4*>(h + (size_t)bin * HID + lane * 4);
        float* dst = acc_u + (size_t)bin * HID + lane * 4;
        atomicAdd(dst + 0, al * hs.x + ar * hd.x);
        atomicAdd(dst + 1, al * hs.y + ar * hd.y);
        atomicAdd(dst + 2, al * hs.z + ar * hd.z);
        atomicAdd(dst + 3, al * hs.w + ar * hd.w);
    }
    __syncthreads();

    // Phase 2: recompute out rows for overflowed bins (idempotent per bin)
    for (int i = w; i < nov; i += 8) {
        int bin = (int)g_ovf[i].x;
        if (bin >= NU) continue;
        float o0 = __ldg(&bout[lane * 2]);
        float o1 = __ldg(&bout[lane * 2 + 1]);
        for (int k = 0; k < HID; k++) {
            float rv = elu1(ldcg(acc_u + (size_t)bin * HID + k));
            o0 += rv * __ldg(&Wout[k * OUT_DIM + lane * 2]);
            o1 += rv * __ldg(&Wout[k * OUT_DIM + lane * 2 + 1]);
        }
        out[(size_t)bin * OUT_DIM + lane * 2]     = o0;
        out[(size_t)bin * OUT_DIM + lane * 2 + 1] = o1;
    }
    __syncthreads();
    if (threadIdx.x == 0) g_ovfn = 0;
}

// ---------------------------------------------------------------------------
// Launch: fork/join DAG (R11 topology, merged cold path).
//   main: prep -> proj -> [join fill] -> bin_acc_user(+GEMM) -> ovf_repair
//   s1:   fill (forked at entry)
//   s2:   bin_acc_item (waits on ev_mid = proj+fill), joined at end
// ---------------------------------------------------------------------------
extern "C" void kernel_launch(void* const* d_in, const int* in_sizes, int n_in,
                              void* d_out, int out_size)
{
    const float* xu    = (const float*)d_in[0];
    const float* xi    = (const float*)d_in[1];
    const float* Wp    = (const float*)d_in[2];
    const float* bp    = (const float*)d_in[3];
    const float* al_uu = (const float*)d_in[4];
    const float* ar_uu = (const float*)d_in[5];
    const float* al_iu = (const float*)d_in[6];
    const float* ar_iu = (const float*)d_in[7];
    const float* al_ui = (const float*)d_in[8];
    const float* ar_ui = (const float*)d_in[9];
    const float* Wo    = (const float*)d_in[10];
    const float* bo    = (const float*)d_in[11];
    const int*   e_uu  = (const int*)d_in[12];
    const int*   e_iu  = (const int*)d_in[13];
    const int*   e_ui  = (const int*)d_in[14];
    const int E_uu = in_sizes[12] / 2;
    const int E_iu = in_sizes[13] / 2;
    const int E_ui = in_sizes[14] / 2;

    float*    h;   cudaGetSymbolAddress((void**)&h,   g_h);
    float*    acc; cudaGetSymbolAddress((void**)&acc, g_acc);
    uint32_t* Wt;  cudaGetSymbolAddress((void**)&Wt,  g_Wt);

    float* out_u = (float*)d_out;
    float* out_i = out_u + (size_t)NU * OUT_DIM;

    static cudaStream_t s1 = nullptr, s2 = nullptr;
    static cudaEvent_t ev_fork, ev_fill, ev_mid, ev_item;
    if (s1 == nullptr) {
        cudaStreamCreateWithFlags(&s1, cudaStreamNonBlocking);
        cudaStreamCreateWithFlags(&s2, cudaStreamNonBlocking);
        cudaEventCreateWithFlags(&ev_fork, cudaEventDisableTiming);
        cudaEventCreateWithFlags(&ev_fill, cudaEventDisableTiming);
        cudaEventCreateWithFlags(&ev_mid, cudaEventDisableTiming);
        cudaEventCreateWithFlags(&ev_item, cudaEventDisableTiming);
        cudaFuncSetAttribute(proj_mma_kernel,
                             cudaFuncAttributeMaxDynamicSharedMemorySize, PROJ_SMEM);
    }

    int totE = E_uu + E_iu + E_ui;

    // Fork fill onto s1
    cudaEventRecord(ev_fork, 0);
    cudaStreamWaitEvent(s1, ev_fork, 0);
    fill_bucket_kernel<<<(totE + 255) / 256, 256, 0, s1>>>(
        (const int2*)e_uu, E_uu, (const int2*)e_iu, E_iu, (const int2*)e_ui, E_ui);
    cudaEventRecord(ev_fill, s1);

    // Main: prep -> proj (concurrent with fill)
    prep_kernel<<<(IN_DIM * HID + 255) / 256, 256>>>(Wp, Wt);
    proj_mma_kernel<<<(M_TOT + BM - 1) / BM, 256, PROJ_SMEM>>>(xu, xi, Wt, bp, h);

    // Join fill; mark the point both branches may start from
    cudaStreamWaitEvent(0, ev_fill, 0);
    cudaEventRecord(ev_mid, 0);

    // Main: user branch (fused GEMM, 3125 blocks)
    bin_acc_user_kernel<<<NU / 16, 256>>>(
        h, al_uu, ar_uu, al_iu, ar_iu, Wo, bo, acc, out_u);

    // Side: item branch, concurrent with user branch
    cudaStreamWaitEvent(s2, ev_mid, 0);
    bin_acc_item_kernel<<<(NI / 2 + 7) / 8, 256, 0, s2>>>(h, al_ui, ar_ui, out_i);
    cudaEventRecord(ev_item, s2);

    // Cold-path overflow handling (after user branch on main)
    ovf_repair_kernel<<<1, 256>>>(h, al_uu, ar_uu, al_iu, ar_iu, acc, Wo, bo, out_u);

    // Join item branch before the harness consumes d_out
    cudaStreamWaitEvent(0, ev_item, 0);
}

// round 15
// speedup vs baseline: 1.4375x; 1.2848x over previous
#include <cuda_runtime.h>
#include <math.h>
#include <stdint.h>

// Problem constants
#define NU      50000
#define NI      50000
#define M_TOT   100000
#define IN_DIM  256
#define HID     128
#define OUT_DIM 64
#define NBIN    (NU + NI)
#define BCAP    32
#define OVF_CAP 8192

// ---------------------------------------------------------------------------
// Device scratch
// ---------------------------------------------------------------------------
__device__ float    g_h[(size_t)M_TOT * HID];
__device__ float    g_acc[(size_t)NU * HID];       // only written on overflow
__device__ uint32_t g_Wt[IN_DIM * HID];            // W_proj tf32 bits, B-frag layout
__device__ uint32_t g_WoF[HID * OUT_DIM];          // W_out tf32 bits, B-frag layout
__device__ int      g_cnt[NBIN];                   // zero-init; re-zeroed by bin_acc
__device__ uint32_t g_bucket[(size_t)NBIN * BCAP];
__device__ int      g_ovfn;                        // reset by ovf_repair
__device__ uint2    g_ovf[OVF_CAP];

__device__ __forceinline__ float elu1(float x) { return x > 0.f ? x : expm1f(x); }

__device__ __forceinline__ uint32_t smem_u32(const void* p) {
    uint32_t a;
    asm("{ .reg .u64 t; cvta.to.shared.u64 t, %1; cvt.u32.u64 %0, t; }" : "=r"(a) : "l"(p));
    return a;
}

__device__ __forceinline__ void cp_async16(uint32_t dst_smem, const void* src) {
    asm volatile("cp.async.cg.shared.global [%0], [%1], 16;"
                 :: "r"(dst_smem), "l"(src) : "memory");
}
#define CP_COMMIT() asm volatile("cp.async.commit_group;" ::: "memory")

__device__ __forceinline__ uint32_t f2tf32(float v) {
    uint32_t t;
    asm("cvt.rna.tf32.f32 %0, %1;" : "=r"(t) : "f"(v));
    return t;
}

__device__ __forceinline__ float ldcg(const float* p) {
    float v;
    asm volatile("ld.global.cg.f32 %0, [%1];" : "=f"(v) : "l"(p));
    return v;
}

__device__ __forceinline__ void mma_tf32(float& d0, float& d1, float& d2, float& d3,
                                         uint32_t a0, uint32_t a1, uint32_t a2, uint32_t a3,
                                         uint32_t b0, uint32_t b1) {
    asm volatile(
        "mma.sync.aligned.m16n8k8.row.col.f32.tf32.tf32.f32 "
        "{%0,%1,%2,%3}, {%4,%5,%6,%7}, {%8,%9}, {%0,%1,%2,%3};"
        : "+f"(d0), "+f"(d1), "+f"(d2), "+f"(d3)
        : "r"(a0), "r"(a1), "r"(a2), "r"(a3), "r"(b0), "r"(b1));
}

// ---------------------------------------------------------------------------
// prep: convert W_proj -> tf32 B-frag layout AND W_out -> tf32 B-frag layout.
// ---------------------------------------------------------------------------
__global__ void prep_kernel(const float* __restrict__ W, uint32_t* __restrict__ Wt,
                            const float* __restrict__ Wout, uint32_t* __restrict__ WoF) {
    int i = blockIdx.x * 256 + threadIdx.x;
    if (i < IN_DIM * HID) {
        int k = i >> 7;
        int n = i & 127;
        int c    = k >> 5;
        int ks   = (k >> 3) & 3;
        int slot = (k >> 2) & 1;
        int tig  = k & 3;
        int wn   = n >> 5;
        int nt   = (n >> 3) & 3;
        int gid  = n & 7;
        int lane = gid * 4 + tig;
        int idx  = c * 4096 + (((ks * 4 + wn) * 4 + nt) * 32 + lane) * 2 + slot;
        Wt[idx] = f2tf32(W[i]);
    } else if (i < IN_DIM * HID + HID * OUT_DIM) {
        int j = i - IN_DIM * HID;            // W_out[k][n], k<128, n<64
        int k = j >> 6;
        int n = j & 63;
        int ks   = k >> 3;                   // 0..15
        int tig  = k & 3;
        int slot = (k >> 2) & 1;
        int wn   = n >> 3;                   // 0..7
        int gid  = n & 7;
        int lane = gid * 4 + tig;
        int idx  = ((ks * 8 + wn) * 32 + lane) * 2 + slot;
        WoF[idx] = f2tf32(Wout[j]);
    }
}

// ---------------------------------------------------------------------------
// Projection via mma.sync tf32, fragment-major smem (unchanged from R9).
// ---------------------------------------------------------------------------
#define KC       32
#define NCHUNK   (IN_DIM / KC)
#define BM       64
#define ASF_W    2112
#define BSF_W    4096
#define PROJ_SMEM ((2 * ASF_W + 2 * BSF_W) * 4)   // 49664 bytes

__device__ __forceinline__ void ldA_regs(const float* __restrict__ xu,
                                         const float* __restrict__ xi,
                                         int m0, int c, int tid, float4* r) {
#pragma unroll
    for (int L = 0; L < 2; L++) {
        int i = tid + L * 256;
        int row = i >> 3;
        int seg = i & 7;
        int gr = m0 + row;
        if (gr >= M_TOT) gr = M_TOT - 1;
        const float* src = (gr < NU) ? (xu + (size_t)gr * IN_DIM)
                                     : (xi + (size_t)(gr - NU) * IN_DIM);
        r[L] = *reinterpret_cast<const float4*>(src + c * KC + seg * 4);
    }
}

__device__ __forceinline__ void stA_smem(uint32_t* __restrict__ As, int tid,
                                         const float4* r) {
#pragma unroll
    for (int L = 0; L < 2; L++) {
        int i = tid + L * 256;
        int row = i >> 3;
        int seg = i & 7;
        int rg    = row >> 4;
        int gid   = row & 7;
        int slotb = (row >> 3) & 1;
        int ks    = seg >> 1;
        int slot  = slotb + 2 * (seg & 1);
        uint32_t* base = As + (rg * 4 + ks) * 132 + gid * 16 + slot;
        base[0]  = f2tf32(r[L].x);
        base[4]  = f2tf32(r[L].y);
        base[8]  = f2tf32(r[L].z);
        base[12] = f2tf32(r[L].w);
    }
}

__device__ __forceinline__ void ldB_cpasync(uint32_t sB, const uint32_t* __restrict__ Wt,
                                            int c, int tid) {
#pragma unroll
    for (int L = 0; L < 4; L++) {
        int i = tid + L * 256;
        cp_async16(sB + i * 16, Wt + (size_t)c * 4096 + i * 4);
    }
    CP_COMMIT();
}

__global__ __launch_bounds__(256, 3) void proj_mma_kernel(
    const float* __restrict__ xu, const float* __restrict__ xi,
    const uint32_t* __restrict__ Wt, const float* __restrict__ bias,
    float* __restrict__ h)
{
    extern __shared__ uint32_t smw[];
    uint32_t sb = smem_u32(smw);
    const int tid  = threadIdx.x;
    const int wid  = tid >> 5;
    const int lane = tid & 31;
    const int gid  = lane >> 2;
    const int tig  = lane & 3;
    const int wm   = wid >> 2;
    const int wn   = wid & 3;
    const int m0   = blockIdx.x * BM;

    float d[2][4][4];
#pragma unroll
    for (int i = 0; i < 2; i++)
#pragma unroll
        for (int j = 0; j < 4; j++)
#pragma unroll
            for (int q = 0; q < 4; q++) d[i][j][q] = 0.f;

    float4 rA[2];
    ldA_regs(xu, xi, m0, 0, tid, rA);
    ldB_cpasync(sb + (2 * ASF_W + 0 * BSF_W) * 4, Wt, 0, tid);
    ldB_cpasync(sb + (2 * ASF_W + 1 * BSF_W) * 4, Wt, 1, tid);

    for (int c = 0; c < NCHUNK; c++) {
        int s = c & 1;
        uint32_t* As = smw + s * ASF_W;
        const uint32_t* Bs = smw + 2 * ASF_W + s * BSF_W;

        stA_smem(As, tid, rA);
        if (c + 1 < NCHUNK) ldA_regs(xu, xi, m0, c + 1, tid, rA);

        if (c < NCHUNK - 1) asm volatile("cp.async.wait_group 1;" ::: "memory");
        else                asm volatile("cp.async.wait_group 0;" ::: "memory");
        __syncthreads();

#pragma unroll
        for (int ks = 0; ks < KC / 8; ks++) {
            uint32_t a[2][4];
#pragma unroll
            for (int mt = 0; mt < 2; mt++) {
                int rg = wm * 2 + mt;
                uint4 av = *reinterpret_cast<const uint4*>(
                    As + (rg * 4 + ks) * 132 + lane * 4);
                a[mt][0] = av.x; a[mt][1] = av.y; a[mt][2] = av.z; a[mt][3] = av.w;
            }
            uint32_t b[4][2];
#pragma unroll
            for (int nt = 0; nt < 4; nt++) {
                uint2 bv = *reinterpret_cast<const uint2*>(
                    Bs + (((ks * 4 + wn) * 4 + nt) * 32 + lane) * 2);
                b[nt][0] = bv.x; b[nt][1] = bv.y;
            }
#pragma unroll
            for (int mt = 0; mt < 2; mt++)
#pragma unroll
                for (int nt = 0; nt < 4; nt++)
                    mma_tf32(d[mt][nt][0], d[mt][nt][1], d[mt][nt][2], d[mt][nt][3],
                             a[mt][0], a[mt][1], a[mt][2], a[mt][3],
                             b[nt][0], b[nt][1]);
        }
        __syncthreads();
        if (c + 2 < NCHUNK)
            ldB_cpasync(sb + (2 * ASF_W + s * BSF_W) * 4, Wt, c + 2, tid);
    }

#pragma unroll
    for (int mt = 0; mt < 2; mt++) {
        int row0 = m0 + wm * 32 + mt * 16 + gid;
        int row1 = row0 + 8;
#pragma unroll
        for (int nt = 0; nt < 4; nt++) {
            int col = wn * 32 + nt * 8 + tig * 2;
            float2 bv = *reinterpret_cast<const float2*>(bias + col);
            if (row0 < M_TOT) {
                float2 v = make_float2(d[mt][nt][0] + bv.x, d[mt][nt][1] + bv.y);
                *reinterpret_cast<float2*>(h + (size_t)row0 * HID + col) = v;
            }
            if (row1 < M_TOT) {
                float2 v = make_float2(d[mt][nt][2] + bv.x, d[mt][nt][3] + bv.y);
                *reinterpret_cast<float2*>(h + (size_t)row1 * HID + col) = v;
            }
        }
    }
}

// ---------------------------------------------------------------------------
// Fill destination buckets from the three edge lists.
// ---------------------------------------------------------------------------
__global__ void fill_bucket_kernel(const int2* __restrict__ e_uu, int Euu,
                                   const int2* __restrict__ e_iu, int Eiu,
                                   const int2* __restrict__ e_ui, int Eui) {
    int e = blockIdx.x * 256 + threadIdx.x;
    int tot = Euu + Eiu + Eui;
    if (e >= tot) return;
    int2 ed;
    int bin;
    uint32_t val;
    if (e < Euu) {
        ed = __ldg(&e_uu[e]);             bin = ed.y;      val = (uint32_t)ed.x;
    } else if (e < Euu + Eiu) {
        ed = __ldg(&e_iu[e - Euu]);       bin = ed.y;      val = (uint32_t)ed.x | 0x80000000u;
    } else {
        ed = __ldg(&e_ui[e - Euu - Eiu]); bin = NU + ed.y; val = (uint32_t)ed.x;
    }
    int pos = atomicAdd(&g_cnt[bin], 1);
    if (pos < BCAP) {
        g_bucket[(size_t)bin * BCAP + pos] = val;
    } else {
        int o = atomicAdd(&g_ovfn, 1);
        if (o < OVF_CAP) g_ovf[o] = make_uint2((uint32_t)bin, val);
    }
}

// ---------------------------------------------------------------------------
// USER bins, fused mma.sync epilogue GEMM. 16 bins/block (m16 tile).
// Each warp: gather 2 bins -> elu -> tf32 -> sA; then one n=8 slice of the
// 16x64x128 output GEMM with m16n8k8 HMMA (16 k-steps).
// ---------------------------------------------------------------------------
__global__ __launch_bounds__(256) void bin_acc_user_kernel(
    const float* __restrict__ h,
    const float* __restrict__ al_uu, const float* __restrict__ ar_uu,
    const float* __restrict__ al_iu, const float* __restrict__ ar_iu,
    const uint32_t* __restrict__ WoF, const float* __restrict__ bout,
    float* __restrict__ acc_u, float* __restrict__ out)
{
    __shared__ uint32_t WsF[HID * OUT_DIM / 1];   // 8192 words = 32 KB (frag layout)
    __shared__ uint32_t sA[16 * 132];             // 8448 B, padded A tile (tf32 bits)

    const int tid  = threadIdx.x;
    const int wid  = tid >> 5;
    const int lane = tid & 31;
    const int gid  = lane >> 2;
    const int tig  = lane & 3;
    const int have_ovf = g_ovfn;

    // Stage W_out fragments (straight copy, already tf32+frag from prep)
#pragma unroll
    for (int L = 0; L < 8; L++) {
        int idx = tid + L * 256;
        reinterpret_cast<uint4*>(WsF)[idx] =
            reinterpret_cast<const uint4*>(WoF)[idx];
    }

    int bin0 = blockIdx.x * 16 + 2 * wid;   // NU = 3125 * 16, exact
    int bin1 = bin0 + 1;

    int n0 = __ldg(&g_cnt[bin0]); if (n0 > BCAP) n0 = BCAP;
    int n1 = __ldg(&g_cnt[bin1]); if (n1 > BCAP) n1 = BCAP;
    if (lane < 2) g_cnt[bin0 + lane] = 0;

    float al0 = 0.f, ar0 = 0.f, al1 = 0.f, ar1 = 0.f;
    uint32_t ro0 = 0, ro1 = 0;
    if (lane < n0) {
        uint32_t v = __ldg(&g_bucket[(size_t)bin0 * BCAP + lane]);
        uint32_t src = v & 0x7FFFFFFFu;
        if (v & 0x80000000u) { al0 = __ldg(al_iu); ar0 = __ldg(ar_iu); ro0 = NU + src; }
        else                 { al0 = __ldg(al_uu); ar0 = __ldg(ar_uu); ro0 = src; }
    }
    if (lane < n1) {
        uint32_t v = __ldg(&g_bucket[(size_t)bin1 * BCAP + lane]);
        uint32_t src = v & 0x7FFFFFFFu;
        if (v & 0x80000000u) { al1 = __ldg(al_iu); ar1 = __ldg(ar_iu); ro1 = NU + src; }
        else                 { al1 = __ldg(al_uu); ar1 = __ldg(ar_uu); ro1 = src; }
    }

    float coef0 = ar0, coef1 = ar1;
#pragma unroll
    for (int o = 16; o; o >>= 1) {
        coef0 += __shfl_xor_sync(0xFFFFFFFFu, coef0, o);
        coef1 += __shfl_xor_sync(0xFFFFFFFFu, coef1, o);
    }

    const float4* h4 = reinterpret_cast<const float4*>(h);
    float4 p0 = make_float4(0.f, 0.f, 0.f, 0.f);
    float4 q0 = make_float4(0.f, 0.f, 0.f, 0.f);
    float4 p1 = make_float4(0.f, 0.f, 0.f, 0.f);
    float4 q1 = make_float4(0.f, 0.f, 0.f, 0.f);

    int nmax = n0 > n1 ? n0 : n1;
    for (int j = 0; j < nmax; j += 2) {
        uint32_t rA0 = __shfl_sync(0xFFFFFFFFu, ro0, j);
        float    aA0 = __shfl_sync(0xFFFFFFFFu, al0, j);
        uint32_t rB0 = __shfl_sync(0xFFFFFFFFu, ro0, (j + 1) & 31);
        float    aB0 = __shfl_sync(0xFFFFFFFFu, al0, (j + 1) & 31);
        uint32_t rA1 = __shfl_sync(0xFFFFFFFFu, ro1, j);
        float    aA1 = __shfl_sync(0xFFFFFFFFu, al1, j);
        uint32_t rB1 = __shfl_sync(0xFFFFFFFFu, ro1, (j + 1) & 31);
        float    aB1 = __shfl_sync(0xFFFFFFFFu, al1, (j + 1) & 31);
        if (j     >= n0) { aA0 = 0.f; rA0 = 0; }
        if (j + 1 >= n0) { aB0 = 0.f; rB0 = 0; }
        if (j     >= n1) { aA1 = 0.f; rA1 = 0; }
        if (j + 1 >= n1) { aB1 = 0.f; rB1 = 0; }
        float4 vA0 = __ldg(h4 + (size_t)rA0 * 32 + lane);
        float4 vB0 = __ldg(h4 + (size_t)rB0 * 32 + lane);
        float4 vA1 = __ldg(h4 + (size_t)rA1 * 32 + lane);
        float4 vB1 = __ldg(h4 + (size_t)rB1 * 32 + lane);
        p0.x += aA0 * vA0.x; p0.y += aA0 * vA0.y; p0.z += aA0 * vA0.z; p0.w += aA0 * vA0.w;
        q0.x += aB0 * vB0.x; q0.y += aB0 * vB0.y; q0.z += aB0 * vB0.z; q0.w += aB0 * vB0.w;
        p1.x += aA1 * vA1.x; p1.y += aA1 * vA1.y; p1.z += aA1 * vA1.z; p1.w += aA1 * vA1.w;
        q1.x += aB1 * vB1.x; q1.y += aB1 * vB1.y; q1.z += aB1 * vB1.z; q1.w += aB1 * vB1.w;
    }

    float4 hd0 = __ldg(h4 + (size_t)bin0 * 32 + lane);
    float4 hd1 = __ldg(h4 + (size_t)bin1 * 32 + lane);
    float4 s0, s1;
    s0.x = p0.x + q0.x + coef0 * hd0.x;
    s0.y = p0.y + q0.y + coef0 * hd0.y;
    s0.z = p0.z + q0.z + coef0 * hd0.z;
    s0.w = p0.w + q0.w + coef0 * hd0.w;
    s1.x = p1.x + q1.x + coef1 * hd1.x;
    s1.y = p1.y + q1.y + coef1 * hd1.y;
    s1.z = p1.z + q1.z + coef1 * hd1.z;
    s1.w = p1.w + q1.w + coef1 * hd1.w;

    if (have_ovf > 0) {
        *reinterpret_cast<float4*>(acc_u + (size_t)bin0 * HID + lane * 4) = s0;
        *reinterpret_cast<float4*>(acc_u + (size_t)bin1 * HID + lane * 4) = s1;
    }

    // elu -> tf32 -> padded A tile (rows 2*wid, 2*wid+1)
    uint4 t0, t1;
    t0.x = f2tf32(elu1(s0.x)); t0.y = f2tf32(elu1(s0.y));
    t0.z = f2tf32(elu1(s0.z)); t0.w = f2tf32(elu1(s0.w));
    t1.x = f2tf32(elu1(s1.x)); t1.y = f2tf32(elu1(s1.y));
    t1.z = f2tf32(elu1(s1.z)); t1.w = f2tf32(elu1(s1.w));
    *reinterpret_cast<uint4*>(sA + (2 * wid)     * 132 + lane * 4) = t0;
    *reinterpret_cast<uint4*>(sA + (2 * wid + 1) * 132 + lane * 4) = t1;
    __syncthreads();

    // Cooperative 16x64x128 GEMM: warp wid handles cols [wid*8, wid*8+8)
    const int wn = wid;
    float d0 = 0.f, d1 = 0.f, d2 = 0.f, d3 = 0.f;
#pragma unroll
    for (int ks = 0; ks < 16; ks++) {
        uint32_t a0 = sA[gid * 132 + ks * 8 + tig];
        uint32_t a1 = sA[(gid + 8) * 132 + ks * 8 + tig];
        uint32_t a2 = sA[gid * 132 + ks * 8 + tig + 4];
        uint32_t a3 = sA[(gid + 8) * 132 + ks * 8 + tig + 4];
        uint2 bb = *reinterpret_cast<const uint2*>(WsF + ((ks * 8 + wn) * 32 + lane) * 2);
        mma_tf32(d0, d1, d2, d3, a0, a1, a2, a3, bb.x, bb.y);
    }
    int base = blockIdx.x * 16;
    float2 bo = *reinterpret_cast<const float2*>(bout + wn * 8 + tig * 2);
    *reinterpret_cast<float2*>(out + (size_t)(base + gid) * OUT_DIM + wn * 8 + tig * 2) =
        make_float2(d0 + bo.x, d1 + bo.y);
    *reinterpret_cast<float2*>(out + (size_t)(base + gid + 8) * OUT_DIM + wn * 8 + tig * 2) =
        make_float2(d2 + bo.x, d3 + bo.y);
}

// ---------------------------------------------------------------------------
// ITEM bins: single relation, elu -> out_i.
// ---------------------------------------------------------------------------
__global__ __launch_bounds__(256) void bin_acc_item_kernel(
    const float* __restrict__ h,
    const float* __restrict__ al_ui, const float* __restrict__ ar_ui,
    float* __restrict__ out_i)
{
    int w = blockIdx.x * 8 + (threadIdx.x >> 5);
    if (w >= NI / 2) return;
    int lane = threadIdx.x & 31;
    int bin0 = NU + 2 * w;
    int bin1 = bin0 + 1;

    const float al = __ldg(al_ui);
    const float ar = __ldg(ar_ui);

    int n0 = __ldg(&g_cnt[bin0]); if (n0 > BCAP) n0 = BCAP;
    int n1 = __ldg(&g_cnt[bin1]); if (n1 > BCAP) n1 = BCAP;
    if (lane < 2) g_cnt[bin0 + lane] = 0;

    uint32_t ro0 = (lane < n0) ? __ldg(&g_bucket[(size_t)bin0 * BCAP + lane]) : 0u;
    uint32_t ro1 = (lane < n1) ? __ldg(&g_bucket[(size_t)bin1 * BCAP + lane]) : 0u;

    const float4* h4 = reinterpret_cast<const float4*>(h);
    float4 p0 = make_float4(0.f, 0.f, 0.f, 0.f);
    float4 q0 = make_float4(0.f, 0.f, 0.f, 0.f);
    float4 p1 = make_float4(0.f, 0.f, 0.f, 0.f);
    float4 q1 = make_float4(0.f, 0.f, 0.f, 0.f);

    int nmax = n0 > n1 ? n0 : n1;
    for (int j = 0; j < nmax; j += 2) {
        uint32_t rA0 = __shfl_sync(0xFFFFFFFFu, ro0, j);
        uint32_t rB0 = __shfl_sync(0xFFFFFFFFu, ro0, (j + 1) & 31);
        uint32_t rA1 = __shfl_sync(0xFFFFFFFFu, ro1, j);
        uint32_t rB1 = __shfl_sync(0xFFFFFFFFu, ro1, (j + 1) & 31);
        float aA0 = (j     < n0) ? al : 0.f; if (j     >= n0) rA0 = 0;
        float aB0 = (j + 1 < n0) ? al : 0.f; if (j + 1 >= n0) rB0 = 0;
        float aA1 = (j     < n1) ? al : 0.f; if (j     >= n1) rA1 = 0;
        float aB1 = (j + 1 < n1) ? al : 0.f; if (j + 1 >= n1) rB1 = 0;
        float4 vA0 = __ldg(h4 + (size_t)rA0 * 32 + lane);
        float4 vB0 = __ldg(h4 + (size_t)rB0 * 32 + lane);
        float4 vA1 = __ldg(h4 + (size_t)rA1 * 32 + lane);
        float4 vB1 = __ldg(h4 + (size_t)rB1 * 32 + lane);
        p0.x += aA0 * vA0.x; p0.y += aA0 * vA0.y; p0.z += aA0 * vA0.z; p0.w += aA0 * vA0.w;
        q0.x += aB0 * vB0.x; q0.y += aB0 * vB0.y; q0.z += aB0 * vB0.z; q0.w += aB0 * vB0.w;
        p1.x += aA1 * vA1.x; p1.y += aA1 * vA1.y; p1.z += aA1 * vA1.z; p1.w += aA1 * vA1.w;
        q1.x += aB1 * vB1.x; q1.y += aB1 * vB1.y; q1.z += aB1 * vB1.z; q1.w += aB1 * vB1.w;
    }

    float coef0 = (float)n0 * ar;
    float coef1 = (float)n1 * ar;
    float4 hd0 = __ldg(h4 + (size_t)bin0 * 32 + lane);
    float4 hd1 = __ldg(h4 + (size_t)bin1 * 32 + lane);
    float4 s0, s1;
    s0.x = elu1(p0.x + q0.x + coef0 * hd0.x);
    s0.y = elu1(p0.y + q0.y + coef0 * hd0.y);
    s0.z = elu1(p0.z + q0.z + coef0 * hd0.z);
    s0.w = elu1(p0.w + q0.w + coef0 * hd0.w);
    s1.x = elu1(p1.x + q1.x + coef1 * hd1.x);
    s1.y = elu1(p1.y + q1.y + coef1 * hd1.y);
    s1.z = elu1(p1.z + q1.z + coef1 * hd1.z);
    s1.w = elu1(p1.w + q1.w + coef1 * hd1.w);

    *reinterpret_cast<float4*>(out_i + (size_t)(bin0 - NU) * HID + lane * 4) = s0;
    *reinterpret_cast<float4*>(out_i + (size_t)(bin1 - NU) * HID + lane * 4) = s1;
}

// ---------------------------------------------------------------------------
// Overflow + repair, single block (cold path; exits immediately when nov==0).
// ---------------------------------------------------------------------------
__global__ __launch_bounds__(256) void ovf_repair_kernel(
    const float* __restrict__ h,
    const float* __restrict__ al_uu, const float* __restrict__ ar_uu,
    const float* __restrict__ al_iu, const float* __restrict__ ar_iu,
    float* __restrict__ acc_u,
    const float* __restrict__ Wout, const float* __restrict__ bout,
    float* __restrict__ out)
{
    int nov = g_ovfn;
    if (nov > OVF_CAP) nov = OVF_CAP;
    if (nov <= 0) return;
    int lane = threadIdx.x & 31;
    int w = threadIdx.x >> 5;

    for (int idx = w; idx < nov; idx += 8) {
        uint2 ov = g_ovf[idx];
        int bin = (int)ov.x;
        if (bin >= NU) continue;
        uint32_t v = ov.y;
        uint32_t src = v & 0x7FFFFFFFu;
        float al, ar;
        size_t row;
        if (v & 0x80000000u) { al = __ldg(al_iu); ar = __ldg(ar_iu); row = (size_t)NU + src; }
        else                 { al = __ldg(al_uu); ar = __ldg(ar_uu); row = src; }
        float4 hs = *reinterpret_cast<const float4*>(h + row * HID + lane * 4);
        float4 hd = *reinterpret_cast<const float4*>(h + (size_t)bin * HID + lane * 4);
        float* dst = acc_u + (size_t)bin * HID + lane * 4;
        atomicAdd(dst + 0, al * hs.x + ar * hd.x);
        atomicAdd(dst + 1, al * hs.y + ar * hd.y);
        atomicAdd(dst + 2, al * hs.z + ar * hd.z);
        atomicAdd(dst + 3, al * hs.w + ar * hd.w);
    }
    __syncthreads();

    for (int i = w; i < nov; i += 8) {
        int bin = (int)g_ovf[i].x;
        if (bin >= NU) continue;
        float o0 = __ldg(&bout[lane * 2]);
        float o1 = __ldg(&bout[lane * 2 + 1]);
        for (int k = 0; k < HID; k++) {
            float rv = elu1(ldcg(acc_u + (size_t)bin * HID + k));
            o0 += rv * __ldg(&Wout[k * OUT_DIM + lane * 2]);
            o1 += rv * __ldg(&Wout[k * OUT_DIM + lane * 2 + 1]);
        }
        out[(size_t)bin * OUT_DIM + lane * 2]     = o0;
        out[(size_t)bin * OUT_DIM + lane * 2 + 1] = o1;
    }
    __syncthreads();
    if (threadIdx.x == 0) g_ovfn = 0;
}

// ---------------------------------------------------------------------------
// Launch: fork/join DAG (R11 ordering: item forked BEFORE user grid).
// ---------------------------------------------------------------------------
extern "C" void kernel_launch(void* const* d_in, const int* in_sizes, int n_in,
                              void* d_out, int out_size)
{
    const float* xu    = (const float*)d_in[0];
    const float* xi    = (const float*)d_in[1];
    const float* Wp    = (const float*)d_in[2];
    const float* bp    = (const float*)d_in[3];
    const float* al_uu = (const float*)d_in[4];
    const float* ar_uu = (const float*)d_in[5];
    const float* al_iu = (const float*)d_in[6];
    const float* ar_iu = (const float*)d_in[7];
    const float* al_ui = (const float*)d_in[8];
    const float* ar_ui = (const float*)d_in[9];
    const float* Wo    = (const float*)d_in[10];
    const float* bo    = (const float*)d_in[11];
    const int*   e_uu  = (const int*)d_in[12];
    const int*   e_iu  = (const int*)d_in[13];
    const int*   e_ui  = (const int*)d_in[14];
    const int E_uu = in_sizes[12] / 2;
    const int E_iu = in_sizes[13] / 2;
    const int E_ui = in_sizes[14] / 2;

    float*    h;   cudaGetSymbolAddress((void**)&h,   g_h);
    float*    acc; cudaGetSymbolAddress((void**)&acc, g_acc);
    uint32_t* Wt;  cudaGetSymbolAddress((void**)&Wt,  g_Wt);
    uint32_t* WoF; cudaGetSymbolAddress((void**)&WoF, g_WoF);

    float* out_u = (float*)d_out;
    float* out_i = out_u + (size_t)NU * OUT_DIM;

    static cudaStream_t s1 = nullptr, s2 = nullptr;
    static cudaEvent_t ev_fork, ev_fill, ev_mid, ev_item;
    if (s1 == nullptr) {
        cudaStreamCreateWithFlags(&s1, cudaStreamNonBlocking);
        cudaStreamCreateWithFlags(&s2, cudaStreamNonBlocking);
        cudaEventCreateWithFlags(&ev_fork, cudaEventDisableTiming);
        cudaEventCreateWithFlags(&ev_fill, cudaEventDisableTiming);
        cudaEventCreateWithFlags(&ev_mid, cudaEventDisableTiming);
        cudaEventCreateWithFlags(&ev_item, cudaEventDisableTiming);
        cudaFuncSetAttribute(proj_mma_kernel,
                             cudaFuncAttributeMaxDynamicSharedMemorySize, PROJ_SMEM);
    }

    int totE = E_uu + E_iu + E_ui;

    // Fork fill onto s1
    cudaEventRecord(ev_fork, 0);
    cudaStreamWaitEvent(s1, ev_fork, 0);
    fill_bucket_kernel<<<(totE + 255) / 256, 256, 0, s1>>>(
        (const int2*)e_uu, E_uu, (const int2*)e_iu, E_iu, (const int2*)e_ui, E_ui);
    cudaEventRecord(ev_fill, s1);

    // Main: prep -> proj (concurrent with fill)
    prep_kernel<<<(IN_DIM * HID + HID * OUT_DIM + 255) / 256, 256>>>(Wp, Wt, Wo, WoF);
    proj_mma_kernel<<<(M_TOT + BM - 1) / BM, 256, PROJ_SMEM>>>(xu, xi, Wt, bp, h);

    // Join fill; fork item branch BEFORE launching the user grid (R11 order)
    cudaStreamWaitEvent(0, ev_fill, 0);
    cudaEventRecord(ev_mid, 0);
    cudaStreamWaitEvent(s2, ev_mid, 0);
    bin_acc_item_kernel<<<(NI / 2 + 7) / 8, 256, 0, s2>>>(h, al_ui, ar_ui, out_i);
    cudaEventRecord(ev_item, s2);

    // Main: user branch (fused mma epilogue)
    bin_acc_user_kernel<<<NU / 16, 256>>>(
        h, al_uu, ar_uu, al_iu, ar_iu, WoF, bo, acc, out_u);

    // Cold-path overflow handling
    ovf_repair_kernel<<<1, 256>>>(h, al_uu, ar_uu, al_iu, ar_iu, acc, Wo, bo, out_u);

    // Join item branch before the harness consumes d_out
    cudaStreamWaitEvent(0, ev_item, 0);
}